// round 15
// baseline (speedup 1.0000x reference)
#include <cuda_runtime.h>
#include <cuda_fp16.h>
#include <mma.h>
#include <math.h>
#include <stdint.h>

using namespace nvcuda;

#define NW 10000
#define MBK 125                 // 80-row m blocks: 125*80 = 10000 exactly
#define KB2 79                  // 128-wide k blocks covering 10112
#define PKB 158                 // 64-row panel tiles covering 10112
#define AT_H 10880              // A tile halves: 80m x 136k
#define T64_H 4608              // panel tile: 64k x 72n
#define T16_H 1536              // panel tile: 64k x 24n
#define SLOT64 40704            // 21760 (A) + 18432 (B) + 512 pad (junk-read overrun)
#define STG64 5
#define SLOT16 27904            // 21760 (A) + 6144 (B)
#define STG16 8

// ---------------- device scratch (static, allocation-free) ----------------
__device__ __align__(16) __half g_A16[(size_t)MBK * KB2 * AT_H]; // tiled A, x256
__device__ __align__(16) __half g_Ph [PKB * T64_H];   // [h] (enc) / [x|h|0] (dec)
__device__ __align__(16) __half g_Prh[PKB * T64_H];
__device__ __align__(16) __half g_Pt [PKB * T64_H];
__device__ __align__(16) __half g_Px0[PKB * T16_H];
__device__ __align__(16) __half g_Px1[PKB * T16_H];
__device__ __align__(16) __half g_lin1[NW * 384];
__device__ __align__(16) __half g_lin2[NW * 384];
__device__ __align__(16) __half g_Wge[384 * 128];  // padded fp16 weights
__device__ __align__(16) __half g_Wce[384 * 64];
__device__ __align__(16) __half g_Wgd[384 * 128];
__device__ __align__(16) __half g_Wcd[384 * 64];
__device__ float g_X1E[NW * 16];
__device__ float g_X2E[NW * 16];
__device__ float g_h[NW * 64];
__device__ float g_u[NW * 64];
__device__ float g_x[NW];

__device__ __forceinline__ size_t t64i(int n, int f) {
    return (size_t)(n >> 6) * T64_H + (size_t)(n & 63) * 72 + f;
}
__device__ __forceinline__ size_t t16i(int n, int f) {
    return (size_t)(n >> 6) * T16_H + (size_t)(n & 63) * 24 + f;
}

// ---------------- A conversion: tiled [125 rb][79 kb][80 m][136 k], x256 ----------------
__global__ void convA(const float* __restrict__ A) {
    size_t total = (size_t)MBK * KB2 * 5440;
    for (size_t j = (size_t)blockIdx.x * blockDim.x + threadIdx.x; j < total;
         j += (size_t)gridDim.x * blockDim.x) {
        size_t tile = j / 5440;
        int w = (int)(j % 5440);
        int m = w / 68, c2 = w % 68;
        int rb = (int)(tile / KB2), kb = (int)(tile % KB2);
        int row = rb * 80 + m, k = kb * 128 + c2 * 2;
        __half2 v = __floats2half2_rn(0.f, 0.f);
        if (c2 < 64 && k + 1 < NW) {
            float2 f = *(const float2*)(A + (size_t)row * NW + k);
            v = __floats2half2_rn(f.x * 256.f, f.y * 256.f);
        }
        *(__half2*)(g_A16 + tile * AT_H + m * 136 + c2 * 2) = v;
    }
}

// weight pad/convert: out[(g*128+kk)*nc+col] = (kk<D) ? W[(g*D+kk)*nc+col] : 0
__global__ void convW(const float* __restrict__ W, __half* __restrict__ out, int D, int nc) {
    int idx = blockIdx.x * blockDim.x + threadIdx.x;
    if (idx >= 384 * nc) return;
    int r = idx / nc, col = idx % nc;
    int g = r >> 7, kk = r & 127;
    float v = (kk < D) ? W[(size_t)(g * D + kk) * nc + col] : 0.f;
    out[idx] = __float2half(v);
}

__global__ void initState() {
    int idx = blockIdx.x * blockDim.x + threadIdx.x;
    if (idx < NW * 64) g_h[idx] = 0.f;
    if (idx < NW) g_x[idx] = 0.f;
    // zero pad nodes 10000..10111 across FULL 72-wide tiles
    if (idx < 3 * 112 * 72) {
        int p = idx / (112 * 72), r = idx % (112 * 72);
        int n = NW + r / 72, f = r % 72;
        __half* P = p == 0 ? g_Ph : (p == 1 ? g_Prh : g_Pt);
        P[t64i(n, f)] = __float2half(0.f);
    }
    if (idx < 2 * 112 * 24) {
        int p = idx / (112 * 24), r = idx % (112 * 24);
        int n = NW + r / 24, f = r % 24;
        __half* P = p == 0 ? g_Px0 : g_Px1;
        P[t16i(n, f)] = __float2half(0.f);
    }
}

__global__ void buildX(const float* __restrict__ inputs) {
    int idx = blockIdx.x * blockDim.x + threadIdx.x;
    if (idx >= NW * 16) return;
    int n = idx >> 4, c = idx & 15;
    g_Px0[t16i(n, c)] = __float2half(c < 12 ? inputs[n * 12 + c] : 0.f);
}

__global__ void buildEncGate(const float* __restrict__ inputs, const float* __restrict__ We,
                             const float* __restrict__ be, int t) {
    int idx = blockIdx.x * blockDim.x + threadIdx.x;
    if (idx >= NW * 64) return;
    int n = idx >> 6, c = idx & 63;
    float w = We[c], b = be[c];
    float h = g_h[n * 64 + c];
    __half* L = g_lin1 + (size_t)n * 384;
    L[c]       = __float2half(inputs[n * 12 + t] * w + b);
    L[64 + c]  = __float2half(h);
    L[128 + c] = __float2half(g_X1E[n * 16 + t] * w + b);
    L[256 + c] = __float2half(g_X2E[n * 16 + t] * w + b);
    g_Ph[t64i(n, c)] = __float2half(h);
}

// dec: Ph tile = [x | h(64) | zeros(7)] per node; lin1 = [x, h...] at cols 0..64
__global__ void buildDecGate() {
    int idx = blockIdx.x * blockDim.x + threadIdx.x;
    if (idx >= NW * 72) return;
    int n = idx / 72, c = idx % 72;
    float v = 0.f;
    if (c == 0)      v = g_x[n];
    else if (c < 65) v = g_h[n * 64 + (c - 1)];
    __half hv = __float2half(v);
    g_Ph[t64i(n, c)] = hv;
    if (c < 65) g_lin1[(size_t)n * 384 + c] = hv;
}

// ---------------- TMA / mbarrier helpers ----------------
__device__ __forceinline__ void bulkcp(uint32_t sdst, const void* gsrc, uint32_t bytes, uint32_t mbar) {
    asm volatile(
        "cp.async.bulk.shared::cluster.global.mbarrier::complete_tx::bytes [%0], [%1], %2, [%3];"
        :: "r"(sdst), "l"(gsrc), "r"(bytes), "r"(mbar) : "memory");
}
__device__ __forceinline__ void mbar_init(uint32_t mbar, uint32_t cnt) {
    asm volatile("mbarrier.init.shared.b64 [%0], %1;" :: "r"(mbar), "r"(cnt) : "memory");
}
__device__ __forceinline__ void mbar_expect(uint32_t mbar, uint32_t bytes) {
    asm volatile("mbarrier.arrive.expect_tx.shared.b64 _, [%0], %1;" :: "r"(mbar), "r"(bytes) : "memory");
}
__device__ __forceinline__ void mbar_arrive(uint32_t mbar) {
    asm volatile("mbarrier.arrive.shared.b64 _, [%0];" :: "r"(mbar) : "memory");
}
__device__ __forceinline__ void mbar_wait(uint32_t mbar, uint32_t parity) {
    asm volatile(
        "{\n\t.reg .pred P;\n\t"
        "W%=:\n\t"
        "mbarrier.try_wait.parity.acquire.cta.shared::cta.b64 P, [%0], %1, 0x989680;\n\t"
        "@P bra D%=;\n\t"
        "bra W%=;\n\t"
        "D%=:\n\t}"
        :: "r"(mbar), "r"(parity) : "memory");
}

// ---------------- bigGemm64: warp-specialized, BK=128 ----------------
// nw5=0: 64 cols (wn*32, 2 frags). nw5=1: 65 valid cols (wn*48, 3 frags, junk cols discarded).
__global__ void __launch_bounds__(352) bigGemm64(const __half* __restrict__ Bt,
                                                 __half* __restrict__ Tout,
                                                 __half* __restrict__ lin,
                                                 int ccol, int ucol, int nw5) {
    extern __shared__ __align__(16) char raw[];
    __shared__ __align__(8) uint64_t mbf[STG64], mbd[STG64];
    const int tid = threadIdx.x, warp = tid >> 5, lane = tid & 31;
    const int row0 = blockIdx.x * 80;
    uint32_t sbase = (uint32_t)__cvta_generic_to_shared(raw);
    uint32_t f0 = (uint32_t)__cvta_generic_to_shared(&mbf[0]);
    uint32_t d0 = (uint32_t)__cvta_generic_to_shared(&mbd[0]);
    const __half* At = g_A16 + (size_t)blockIdx.x * KB2 * AT_H;

    if (tid == 0)
        for (int s = 0; s < STG64; s++) { mbar_init(f0 + s * 8, 1); mbar_init(d0 + s * 8, 10); }
    __syncthreads();

    if (warp == 10) {
        if (lane == 0) {
            for (int j = 0; j < KB2; j++) {
                int s = j % STG64;
                if (j >= STG64) mbar_wait(d0 + s * 8, (uint32_t)((j / STG64 - 1) & 1));
                mbar_expect(f0 + s * 8, SLOT64 - 512);
                bulkcp(sbase + s * SLOT64, At + (size_t)j * AT_H, 21760, f0 + s * 8);
                bulkcp(sbase + s * SLOT64 + 21760, Bt + (size_t)(2 * j) * T64_H, 18432, f0 + s * 8);
            }
        }
    } else {
        const int wm = warp % 5, wn = warp / 5;
        const int nj = nw5 ? 3 : 2;
        const int ncw = nw5 ? 48 : 32;
        wmma::fragment<wmma::accumulator, 16, 16, 16, float> acc[3];
#pragma unroll
        for (int j = 0; j < 3; j++) wmma::fill_fragment(acc[j], 0.f);
        for (int i = 0; i < KB2; i++) {
            int s = i % STG64;
            mbar_wait(f0 + s * 8, (uint32_t)((i / STG64) & 1));
            const __half* As = (const __half*)(raw + s * SLOT64);
            const __half* Bs = As + 10880;
#pragma unroll
            for (int kk = 0; kk < 128; kk += 16) {
                wmma::fragment<wmma::matrix_a, 16, 16, 16, __half, wmma::row_major> af;
                wmma::load_matrix_sync(af, As + (wm * 16) * 136 + kk, 136);
                for (int j = 0; j < nj; j++) {
                    wmma::fragment<wmma::matrix_b, 16, 16, 16, __half, wmma::row_major> bf;
                    wmma::load_matrix_sync(bf, Bs + kk * 72 + wn * ncw + j * 16, 72);
                    wmma::mma_sync(acc[j], af, bf, acc[j]);
                }
            }
            if (lane == 0) mbar_arrive(d0 + s * 8);
        }
        __syncthreads();
        float* Cw = (float*)raw + warp * 768;   // up to 16x48 per warp
        for (int j = 0; j < nj; j++)
            wmma::store_matrix_sync(Cw + j * 16, acc[j], ncw, wmma::mem_row_major);
        __syncwarp();
        const float sc = 1.f / 256.f;
        const int nvalid = nw5 ? 65 : 64;
#pragma unroll
        for (int r = 0; r < 16; r++) {
            int node = row0 + wm * 16 + r;
            for (int cc = lane; cc < ncw; cc += 32) {
                int col = wn * ncw + cc;
                if (col >= nvalid) continue;
                float v = Cw[r * ncw + cc] * sc;
                if (ucol >= 0)
                    v = 2.f * v - __half2float(lin[(size_t)node * 384 + ucol + col]);
                __half hv = __float2half(v);
                lin[(size_t)node * 384 + ccol + col] = hv;
                if (Tout) Tout[t64i(node, col)] = hv;
            }
        }
        return;
    }
    __syncthreads();
}

// ---------------- bigGemm16: warp-specialized, BK=128 (enc prologue only) ----------------
__global__ void __launch_bounds__(192) bigGemm16(const __half* __restrict__ Bt,
                                                 __half* __restrict__ Tout,
                                                 float* __restrict__ out16,
                                                 const float* __restrict__ uptr,
                                                 int ustride, int uncols) {
    extern __shared__ __align__(16) char raw[];
    __shared__ __align__(8) uint64_t mbf[STG16], mbd[STG16];
    const int tid = threadIdx.x, warp = tid >> 5, lane = tid & 31;
    const int row0 = blockIdx.x * 80;
    uint32_t sbase = (uint32_t)__cvta_generic_to_shared(raw);
    uint32_t f0 = (uint32_t)__cvta_generic_to_shared(&mbf[0]);
    uint32_t d0 = (uint32_t)__cvta_generic_to_shared(&mbd[0]);
    const __half* At = g_A16 + (size_t)blockIdx.x * KB2 * AT_H;

    if (tid == 0)
        for (int s = 0; s < STG16; s++) { mbar_init(f0 + s * 8, 1); mbar_init(d0 + s * 8, 5); }
    __syncthreads();

    if (warp == 5) {
        if (lane == 0) {
            for (int j = 0; j < KB2; j++) {
                int s = j % STG16;
                if (j >= STG16) mbar_wait(d0 + s * 8, (uint32_t)((j / STG16 - 1) & 1));
                mbar_expect(f0 + s * 8, SLOT16);
                bulkcp(sbase + s * SLOT16, At + (size_t)j * AT_H, 21760, f0 + s * 8);
                bulkcp(sbase + s * SLOT16 + 21760, Bt + (size_t)(2 * j) * T16_H, 6144, f0 + s * 8);
            }
        }
    } else {
        wmma::fragment<wmma::accumulator, 16, 16, 16, float> acc;
        wmma::fill_fragment(acc, 0.f);
        for (int i = 0; i < KB2; i++) {
            int s = i % STG16;
            mbar_wait(f0 + s * 8, (uint32_t)((i / STG16) & 1));
            const __half* As = (const __half*)(raw + s * SLOT16);
            const __half* Bs = As + 10880;
#pragma unroll
            for (int kk = 0; kk < 128; kk += 16) {
                wmma::fragment<wmma::matrix_a, 16, 16, 16, __half, wmma::row_major> af;
                wmma::load_matrix_sync(af, As + (warp * 16) * 136 + kk, 136);
                wmma::fragment<wmma::matrix_b, 16, 16, 16, __half, wmma::row_major> bf;
                wmma::load_matrix_sync(bf, Bs + kk * 24, 24);
                wmma::mma_sync(acc, af, bf, acc);
            }
            if (lane == 0) mbar_arrive(d0 + s * 8);
        }
        __syncthreads();
        float* Cw = (float*)raw + warp * 256;
        wmma::store_matrix_sync(Cw, acc, 16, wmma::mem_row_major);
        __syncwarp();
        if (lane < 16) {
            const float sc = 1.f / 256.f;
#pragma unroll
            for (int r = 0; r < 16; r++) {
                int node = row0 + warp * 16 + r;
                int col = lane;
                float v = Cw[r * 16 + col] * sc;
                if (uptr && col < uncols)
                    v = 2.f * v - uptr[(size_t)node * ustride + col];
                else if (uptr)
                    v = 2.f * v;
                out16[(size_t)node * 16 + col] = v;
                if (Tout) Tout[t16i(node, col)] = __float2half(v);
            }
        }
        return;
    }
    __syncthreads();
}

// ---------------- gates GEMM (wmma) ----------------
__global__ void __launch_bounds__(320) wgemmGatesT(const __half* __restrict__ lin1,
                                                   __half* __restrict__ lin2,
                                                   const __half* __restrict__ Wh,
                                                   const float* __restrict__ bias, int dec) {
    extern __shared__ __align__(16) char raw[];
    __half* As = (__half*)raw;                       // 80 x 392
    __half* Bs = (__half*)(raw + 80 * 392 * 2);      // 384 x 136
    const int tid = threadIdx.x, warp = tid >> 5, lane = tid & 31;
    const int row0 = blockIdx.x * 80;

    for (int i = tid; i < 80 * 48; i += 320) {
        int r = i / 48, q = i % 48;
        ((float4*)(As + r * 392))[q] = ((const float4*)(lin1 + (size_t)(row0 + r) * 384))[q];
    }
    for (int i = tid; i < 384 * 16; i += 320) {
        int r = i / 16, q = i % 16;
        ((float4*)(Bs + r * 136))[q] = ((const float4*)(Wh + (size_t)r * 128))[q];
    }
    __syncthreads();

    const int wm = warp % 5, wn = warp / 5;
    wmma::fragment<wmma::accumulator, 16, 16, 16, float> acc[4];
#pragma unroll
    for (int j = 0; j < 4; j++) wmma::fill_fragment(acc[j], 0.f);
#pragma unroll 4
    for (int k = 0; k < 384; k += 16) {
        wmma::fragment<wmma::matrix_a, 16, 16, 16, __half, wmma::row_major> af;
        wmma::load_matrix_sync(af, As + (wm * 16) * 392 + k, 392);
#pragma unroll
        for (int j = 0; j < 4; j++) {
            wmma::fragment<wmma::matrix_b, 16, 16, 16, __half, wmma::row_major> bf;
            wmma::load_matrix_sync(bf, Bs + k * 136 + wn * 64 + j * 16, 136);
            wmma::mma_sync(acc[j], af, bf, acc[j]);
        }
    }
    __syncthreads();
    float* Cw = (float*)Bs + warp * 1024;
#pragma unroll
    for (int j = 0; j < 4; j++)
        wmma::store_matrix_sync(Cw + j * 16, acc[j], 64, wmma::mem_row_major);
    __syncwarp();

#pragma unroll
    for (int r = 0; r < 16; r++) {
        int node = row0 + wm * 16 + r;
        const __half* Ar = As + (wm * 16 + r) * 392;
        __half* L2 = lin2 + (size_t)node * 384;
#pragma unroll
        for (int hh = 0; hh < 2; hh++) {
            int c = lane + hh * 32;
            float v = Cw[r * 64 + c] + bias[wn * 64 + c];
            float sig = 1.f / (1.f + __expf(-v));
            if (wn == 0) {
                __half rh = __float2half(sig * g_h[node * 64 + c]);
                g_Prh[t64i(node, c)] = rh;
                if (!dec) {
                    L2[c] = Ar[c];  L2[64 + c] = rh;
                    L2[128 + c] = Ar[128 + c];  L2[256 + c] = Ar[256 + c];
                } else {
                    L2[1 + c] = rh;
                    if (c == 0) { L2[0] = Ar[0]; L2[128] = Ar[128]; L2[256] = Ar[256]; }
                }
            } else {
                g_u[node * 64 + c] = sig;
            }
        }
    }
}

// ---------------- cand GEMM (wmma) + GRU update ----------------
__global__ void __launch_bounds__(320) wgemmCandT(const __half* __restrict__ lin2,
                                                  const __half* __restrict__ Wch,
                                                  const float* __restrict__ bias) {
    extern __shared__ __align__(16) char raw[];
    __half* As = (__half*)raw;                       // 80 x 392
    __half* Bs = (__half*)(raw + 80 * 392 * 2);      // 384 x 72
    const int tid = threadIdx.x, warp = tid >> 5, lane = tid & 31;
    const int row0 = blockIdx.x * 80;

    for (int i = tid; i < 80 * 48; i += 320) {
        int r = i / 48, q = i % 48;
        ((float4*)(As + r * 392))[q] = ((const float4*)(lin2 + (size_t)(row0 + r) * 384))[q];
    }
    for (int i = tid; i < 384 * 8; i += 320) {
        int r = i / 8, q = i % 8;
        ((float4*)(Bs + r * 72))[q] = ((const float4*)(Wch + (size_t)r * 64))[q];
    }
    __syncthreads();

    const int wm = warp % 5, wn = warp / 5;
    wmma::fragment<wmma::accumulator, 16, 16, 16, float> acc[2];
    wmma::fill_fragment(acc[0], 0.f);
    wmma::fill_fragment(acc[1], 0.f);
#pragma unroll 4
    for (int k = 0; k < 384; k += 16) {
        wmma::fragment<wmma::matrix_a, 16, 16, 16, __half, wmma::row_major> af;
        wmma::load_matrix_sync(af, As + (wm * 16) * 392 + k, 392);
#pragma unroll
        for (int j = 0; j < 2; j++) {
            wmma::fragment<wmma::matrix_b, 16, 16, 16, __half, wmma::row_major> bf;
            wmma::load_matrix_sync(bf, Bs + k * 72 + wn * 32 + j * 16, 72);
            wmma::mma_sync(acc[j], af, bf, acc[j]);
        }
    }
    __syncthreads();
    float* Cw = (float*)Bs + warp * 512;
    wmma::store_matrix_sync(Cw, acc[0], 32, wmma::mem_row_major);
    wmma::store_matrix_sync(Cw + 16, acc[1], 32, wmma::mem_row_major);
    __syncwarp();

#pragma unroll
    for (int r = 0; r < 16; r++) {
        int node = row0 + wm * 16 + r;
        int col = wn * 32 + lane;
        float v = Cw[r * 32 + lane] + bias[col];
        float c = tanhf(v);
        float u = g_u[node * 64 + col];
        float hOld = g_h[node * 64 + col];
        g_h[node * 64 + col] = u * hOld + (1.f - u) * c;
    }
}

// ---------------- prediction ----------------
__global__ void predKernel(const float* __restrict__ Wp, const float* __restrict__ bp,
                           float* __restrict__ out, int t) {
    int gwarp = (blockIdx.x * blockDim.x + threadIdx.x) >> 5;
    int lane = threadIdx.x & 31;
    if (gwarp >= NW) return;
    float s = g_h[gwarp * 64 + lane] * Wp[lane] + g_h[gwarp * 64 + 32 + lane] * Wp[32 + lane];
#pragma unroll
    for (int o = 16; o; o >>= 1) s += __shfl_xor_sync(0xFFFFFFFFu, s, o);
    if (lane == 0) {
        float val = s + bp[0];
        out[gwarp * 12 + t] = val;
        g_x[gwarp] = val;
    }
}

// ---------------- launch ----------------
extern "C" void kernel_launch(void* const* d_in, const int* in_sizes, int n_in,
                              void* d_out, int out_size) {
    const float* inputs = (const float*)d_in[0];
    const float* adj    = (const float*)d_in[2];
    const float* W_emb  = (const float*)d_in[3];
    const float* b_emb  = (const float*)d_in[4];
    const float* Wg_e   = (const float*)d_in[5];
    const float* bg_e   = (const float*)d_in[6];
    const float* Wc_e   = (const float*)d_in[7];
    const float* bc_e   = (const float*)d_in[8];
    const float* Wg_d   = (const float*)d_in[9];
    const float* bg_d   = (const float*)d_in[10];
    const float* Wc_d   = (const float*)d_in[11];
    const float* bc_d   = (const float*)d_in[12];
    const float* W_pred = (const float*)d_in[13];
    const float* b_pred = (const float*)d_in[14];
    float* out = (float*)d_out;

    __half *Ph, *Prh, *Pt, *Px0, *Px1, *lin1, *lin2;
    __half *Wge, *Wce, *Wgd, *Wcd;
    float *X1E, *X2E;
    cudaGetSymbolAddress((void**)&Ph, g_Ph);
    cudaGetSymbolAddress((void**)&Prh, g_Prh);
    cudaGetSymbolAddress((void**)&Pt, g_Pt);
    cudaGetSymbolAddress((void**)&Px0, g_Px0);
    cudaGetSymbolAddress((void**)&Px1, g_Px1);
    cudaGetSymbolAddress((void**)&lin1, g_lin1);
    cudaGetSymbolAddress((void**)&lin2, g_lin2);
    cudaGetSymbolAddress((void**)&Wge, g_Wge);
    cudaGetSymbolAddress((void**)&Wce, g_Wce);
    cudaGetSymbolAddress((void**)&Wgd, g_Wgd);
    cudaGetSymbolAddress((void**)&Wcd, g_Wcd);
    cudaGetSymbolAddress((void**)&X1E, g_X1E);
    cudaGetSymbolAddress((void**)&X2E, g_X2E);

    const int sm64 = STG64 * SLOT64;                 // 203520
    const int sm16 = STG16 * SLOT16;                 // 223232
    const int smG  = 80 * 392 * 2 + 384 * 136 * 2;   // 167168
    const int smC  = 80 * 392 * 2 + 384 * 72 * 2;    // 118016
    cudaFuncSetAttribute(bigGemm64, cudaFuncAttributeMaxDynamicSharedMemorySize, sm64);
    cudaFuncSetAttribute(bigGemm16, cudaFuncAttributeMaxDynamicSharedMemorySize, sm16);
    cudaFuncSetAttribute(wgemmGatesT, cudaFuncAttributeMaxDynamicSharedMemorySize, smG);
    cudaFuncSetAttribute(wgemmCandT, cudaFuncAttributeMaxDynamicSharedMemorySize, smC);

    convA<<<4096, 256>>>(adj);
    initState<<<(NW * 64 + 255) / 256, 256>>>();
    buildX<<<(NW * 16 + 255) / 256, 256>>>(inputs);
    convW<<<(384 * 128 + 255) / 256, 256>>>(Wg_e, Wge, 128, 128);
    convW<<<(384 * 64 + 255) / 256, 256>>>(Wc_e, Wce, 128, 64);
    convW<<<(384 * 128 + 255) / 256, 256>>>(Wg_d, Wgd, 65, 128);
    convW<<<(384 * 64 + 255) / 256, 256>>>(Wc_d, Wcd, 65, 64);
    bigGemm16<<<MBK, 192, sm16>>>(Px0, Px1, X1E, nullptr, 0, 0);
    bigGemm16<<<MBK, 192, sm16>>>(Px1, nullptr, X2E, inputs, 12, 12);

    for (int t = 0; t < 12; t++) {
        buildEncGate<<<(NW * 64 + 255) / 256, 256>>>(inputs, W_emb, b_emb, t);
        bigGemm64<<<MBK, 352, sm64>>>(Ph, Pt, lin1, 192, -1, 0);
        bigGemm64<<<MBK, 352, sm64>>>(Pt, nullptr, lin1, 320, 64, 0);
        wgemmGatesT<<<MBK, 320, smG>>>(lin1, lin2, Wge, bg_e, 0);
        bigGemm64<<<MBK, 352, sm64>>>(Prh, Pt, lin2, 192, -1, 0);
        bigGemm64<<<MBK, 352, sm64>>>(Pt, nullptr, lin2, 320, 64, 0);
        wgemmCandT<<<MBK, 320, smC>>>(lin2, Wce, bc_e);
    }
    for (int t = 0; t < 12; t++) {
        buildDecGate<<<(NW * 72 + 255) / 256, 256>>>();
        bigGemm64<<<MBK, 352, sm64>>>(Ph, Pt, lin1, 128, -1, 1);   // A@[x|h] -> 65 cols
        bigGemm64<<<MBK, 352, sm64>>>(Pt, nullptr, lin1, 256, 0, 1);
        wgemmGatesT<<<MBK, 320, smG>>>(lin1, lin2, Wgd, bg_d, 1);
        bigGemm64<<<MBK, 352, sm64>>>(Prh, Pt, lin2, 129, -1, 0);
        bigGemm64<<<MBK, 352, sm64>>>(Pt, nullptr, lin2, 257, 1, 0);
        wgemmCandT<<<MBK, 320, smC>>>(lin2, Wcd, bc_d);
        predKernel<<<(NW + 3) / 4, 128>>>(W_pred, b_pred, out, t);
    }
}

// round 16
// speedup vs baseline: 1.2405x; 1.2405x over previous
#include <cuda_runtime.h>
#include <cuda_fp16.h>
#include <mma.h>
#include <math.h>
#include <stdint.h>

using namespace nvcuda;

#define NW 10000
#define MBK 125                 // 80-row m blocks: 125*80 = 10000 exactly
#define KB2 79                  // 128-wide k blocks covering 10112
#define PKB 158                 // 64-row panel tiles covering 10112
#define AT_H 10880              // A tile halves: 80m x 136k
#define T64_H 4608              // panel tile: 64k x 72n
#define T16_H 1536              // panel tile: 64k x 24n
#define SLOT64 40704            // 21760 (A) + 18432 (B) + 512 pad (junk-read overrun)
#define STG64 5
#define SLOT16 27904            // 21760 (A) + 6144 (B)
#define STG16 8

// ---------------- device scratch (static, allocation-free) ----------------
__device__ __align__(16) __half g_A16[(size_t)MBK * KB2 * AT_H]; // tiled A, x256
__device__ __align__(16) __half g_Ph [PKB * T64_H];   // [h] (enc) / [x|h|0] (dec)
__device__ __align__(16) __half g_Prh[PKB * T64_H];
__device__ __align__(16) __half g_Pt [PKB * T64_H];
__device__ __align__(16) __half g_Px0[PKB * T16_H];
__device__ __align__(16) __half g_Px1[PKB * T16_H];
__device__ __align__(16) __half g_lin1[NW * 384];
__device__ __align__(16) __half g_lin2[NW * 384];
__device__ __align__(16) __half g_Wge[384 * 128];  // padded fp16 weights
__device__ __align__(16) __half g_Wce[384 * 64];
__device__ __align__(16) __half g_Wgd[384 * 128];
__device__ __align__(16) __half g_Wcd[384 * 64];
__device__ float g_X1E[NW * 16];
__device__ float g_X2E[NW * 16];
__device__ float g_h[NW * 64];
__device__ float g_u[NW * 64];
__device__ float g_x[NW];

__device__ __forceinline__ size_t t64i(int n, int f) {
    return (size_t)(n >> 6) * T64_H + (size_t)(n & 63) * 72 + f;
}
__device__ __forceinline__ size_t t16i(int n, int f) {
    return (size_t)(n >> 6) * T16_H + (size_t)(n & 63) * 24 + f;
}

// ---------------- A conversion: tiled [125 rb][79 kb][80 m][136 k], x256 ----------------
__global__ void convA(const float* __restrict__ A) {
    size_t total = (size_t)MBK * KB2 * 5440;
    for (size_t j = (size_t)blockIdx.x * blockDim.x + threadIdx.x; j < total;
         j += (size_t)gridDim.x * blockDim.x) {
        size_t tile = j / 5440;
        int w = (int)(j % 5440);
        int m = w / 68, c2 = w % 68;
        int rb = (int)(tile / KB2), kb = (int)(tile % KB2);
        int row = rb * 80 + m, k = kb * 128 + c2 * 2;
        __half2 v = __floats2half2_rn(0.f, 0.f);
        if (c2 < 64 && k + 1 < NW) {
            float2 f = *(const float2*)(A + (size_t)row * NW + k);
            v = __floats2half2_rn(f.x * 256.f, f.y * 256.f);
        }
        *(__half2*)(g_A16 + tile * AT_H + m * 136 + c2 * 2) = v;
    }
}

// weight pad/convert
__global__ void convW(const float* __restrict__ W, __half* __restrict__ out, int D, int nc) {
    int idx = blockIdx.x * blockDim.x + threadIdx.x;
    if (idx >= 384 * nc) return;
    int r = idx / nc, col = idx % nc;
    int g = r >> 7, kk = r & 127;
    float v = (kk < D) ? W[(size_t)(g * D + kk) * nc + col] : 0.f;
    out[idx] = __float2half(v);
}

__global__ void initState() {
    int idx = blockIdx.x * blockDim.x + threadIdx.x;
    if (idx < NW * 64) g_h[idx] = 0.f;
    if (idx < NW) g_x[idx] = 0.f;
    if (idx < 3 * 112 * 72) {
        int p = idx / (112 * 72), r = idx % (112 * 72);
        int n = NW + r / 72, f = r % 72;
        __half* P = p == 0 ? g_Ph : (p == 1 ? g_Prh : g_Pt);
        P[t64i(n, f)] = __float2half(0.f);
    }
    if (idx < 2 * 112 * 24) {
        int p = idx / (112 * 24), r = idx % (112 * 24);
        int n = NW + r / 24, f = r % 24;
        __half* P = p == 0 ? g_Px0 : g_Px1;
        P[t16i(n, f)] = __float2half(0.f);
    }
}

__global__ void buildX(const float* __restrict__ inputs) {
    int idx = blockIdx.x * blockDim.x + threadIdx.x;
    if (idx >= NW * 16) return;
    int n = idx >> 4, c = idx & 15;
    g_Px0[t16i(n, c)] = __float2half(c < 12 ? inputs[n * 12 + c] : 0.f);
}

__global__ void buildEncGate(const float* __restrict__ inputs, const float* __restrict__ We,
                             const float* __restrict__ be, int t) {
    int idx = blockIdx.x * blockDim.x + threadIdx.x;
    if (idx >= NW * 64) return;
    int n = idx >> 6, c = idx & 63;
    float w = We[c], b = be[c];
    float h = g_h[n * 64 + c];
    __half* L = g_lin1 + (size_t)n * 384;
    L[c]       = __float2half(inputs[n * 12 + t] * w + b);
    L[64 + c]  = __float2half(h);
    L[128 + c] = __float2half(g_X1E[n * 16 + t] * w + b);
    L[256 + c] = __float2half(g_X2E[n * 16 + t] * w + b);
    g_Ph[t64i(n, c)] = __float2half(h);
}

// dec: Ph tile = [x | h(64) | zeros(7)] per node; lin1 = [x, h...] at cols 0..64
__global__ void buildDecGate() {
    int idx = blockIdx.x * blockDim.x + threadIdx.x;
    if (idx >= NW * 72) return;
    int n = idx / 72, c = idx % 72;
    float v = 0.f;
    if (c == 0)      v = g_x[n];
    else if (c < 65) v = g_h[n * 64 + (c - 1)];
    __half hv = __float2half(v);
    g_Ph[t64i(n, c)] = hv;
    if (c < 65) g_lin1[(size_t)n * 384 + c] = hv;
}

// ---------------- TMA / mbarrier helpers ----------------
__device__ __forceinline__ void bulkcp(uint32_t sdst, const void* gsrc, uint32_t bytes, uint32_t mbar) {
    asm volatile(
        "cp.async.bulk.shared::cluster.global.mbarrier::complete_tx::bytes [%0], [%1], %2, [%3];"
        :: "r"(sdst), "l"(gsrc), "r"(bytes), "r"(mbar) : "memory");
}
__device__ __forceinline__ void mbar_init(uint32_t mbar, uint32_t cnt) {
    asm volatile("mbarrier.init.shared.b64 [%0], %1;" :: "r"(mbar), "r"(cnt) : "memory");
}
__device__ __forceinline__ void mbar_expect(uint32_t mbar, uint32_t bytes) {
    asm volatile("mbarrier.arrive.expect_tx.shared.b64 _, [%0], %1;" :: "r"(mbar), "r"(bytes) : "memory");
}
__device__ __forceinline__ void mbar_arrive(uint32_t mbar) {
    asm volatile("mbarrier.arrive.shared.b64 _, [%0];" :: "r"(mbar) : "memory");
}
__device__ __forceinline__ void mbar_wait(uint32_t mbar, uint32_t parity) {
    asm volatile(
        "{\n\t.reg .pred P;\n\t"
        "W%=:\n\t"
        "mbarrier.try_wait.parity.acquire.cta.shared::cta.b64 P, [%0], %1, 0x989680;\n\t"
        "@P bra D%=;\n\t"
        "bra W%=;\n\t"
        "D%=:\n\t}"
        :: "r"(mbar), "r"(parity) : "memory");
}

// ---------------- bigGemm64: warp-specialized, BK=128, 64 cols (R13-exact mainloop) ----------------
__global__ void __launch_bounds__(352) bigGemm64(const __half* __restrict__ Bt,
                                                 __half* __restrict__ Tout,
                                                 __half* __restrict__ lin,
                                                 int ccol, int ucol) {
    extern __shared__ __align__(16) char raw[];
    __shared__ __align__(8) uint64_t mbf[STG64], mbd[STG64];
    const int tid = threadIdx.x, warp = tid >> 5, lane = tid & 31;
    const int row0 = blockIdx.x * 80;
    uint32_t sbase = (uint32_t)__cvta_generic_to_shared(raw);
    uint32_t f0 = (uint32_t)__cvta_generic_to_shared(&mbf[0]);
    uint32_t d0 = (uint32_t)__cvta_generic_to_shared(&mbd[0]);
    const __half* At = g_A16 + (size_t)blockIdx.x * KB2 * AT_H;

    if (tid == 0)
        for (int s = 0; s < STG64; s++) { mbar_init(f0 + s * 8, 1); mbar_init(d0 + s * 8, 10); }
    __syncthreads();

    if (warp == 10) {
        if (lane == 0) {
            for (int j = 0; j < KB2; j++) {
                int s = j % STG64;
                if (j >= STG64) mbar_wait(d0 + s * 8, (uint32_t)((j / STG64 - 1) & 1));
                mbar_expect(f0 + s * 8, SLOT64 - 512);
                bulkcp(sbase + s * SLOT64, At + (size_t)j * AT_H, 21760, f0 + s * 8);
                bulkcp(sbase + s * SLOT64 + 21760, Bt + (size_t)(2 * j) * T64_H, 18432, f0 + s * 8);
            }
        }
    } else {
        const int wm = warp % 5, wn = warp / 5;
        wmma::fragment<wmma::accumulator, 16, 16, 16, float> acc[2];
        wmma::fill_fragment(acc[0], 0.f);
        wmma::fill_fragment(acc[1], 0.f);
        for (int i = 0; i < KB2; i++) {
            int s = i % STG64;
            mbar_wait(f0 + s * 8, (uint32_t)((i / STG64) & 1));
            const __half* As = (const __half*)(raw + s * SLOT64);
            const __half* Bs = As + 10880;
#pragma unroll
            for (int kk = 0; kk < 128; kk += 16) {
                wmma::fragment<wmma::matrix_a, 16, 16, 16, __half, wmma::row_major> af;
                wmma::load_matrix_sync(af, As + (wm * 16) * 136 + kk, 136);
#pragma unroll
                for (int j = 0; j < 2; j++) {
                    wmma::fragment<wmma::matrix_b, 16, 16, 16, __half, wmma::row_major> bf;
                    wmma::load_matrix_sync(bf, Bs + kk * 72 + wn * 32 + j * 16, 72);
                    wmma::mma_sync(acc[j], af, bf, acc[j]);
                }
            }
            if (lane == 0) mbar_arrive(d0 + s * 8);
        }
        __syncthreads();
        float* Cw = (float*)raw + warp * 512;
        wmma::store_matrix_sync(Cw, acc[0], 32, wmma::mem_row_major);
        wmma::store_matrix_sync(Cw + 16, acc[1], 32, wmma::mem_row_major);
        __syncwarp();
        const float sc = 1.f / 256.f;
#pragma unroll
        for (int r = 0; r < 16; r++) {
            int node = row0 + wm * 16 + r;
            int col = wn * 32 + lane;
            float v = Cw[r * 32 + lane] * sc;
            if (ucol >= 0)
                v = 2.f * v - __half2float(lin[(size_t)node * 384 + ucol + col]);
            __half hv = __float2half(v);
            lin[(size_t)node * 384 + ccol + col] = hv;
            if (Tout) Tout[t64i(node, col)] = hv;
        }
        return;
    }
    __syncthreads();
}

// ---------------- bigGemm65: same engine, hardcoded 3 frags / 48 cols per warp (dec gates) ----------------
__global__ void __launch_bounds__(352) bigGemm65(const __half* __restrict__ Bt,
                                                 __half* __restrict__ Tout,
                                                 __half* __restrict__ lin,
                                                 int ccol, int ucol) {
    extern __shared__ __align__(16) char raw[];
    __shared__ __align__(8) uint64_t mbf[STG64], mbd[STG64];
    const int tid = threadIdx.x, warp = tid >> 5, lane = tid & 31;
    const int row0 = blockIdx.x * 80;
    uint32_t sbase = (uint32_t)__cvta_generic_to_shared(raw);
    uint32_t f0 = (uint32_t)__cvta_generic_to_shared(&mbf[0]);
    uint32_t d0 = (uint32_t)__cvta_generic_to_shared(&mbd[0]);
    const __half* At = g_A16 + (size_t)blockIdx.x * KB2 * AT_H;

    if (tid == 0)
        for (int s = 0; s < STG64; s++) { mbar_init(f0 + s * 8, 1); mbar_init(d0 + s * 8, 10); }
    __syncthreads();

    if (warp == 10) {
        if (lane == 0) {
            for (int j = 0; j < KB2; j++) {
                int s = j % STG64;
                if (j >= STG64) mbar_wait(d0 + s * 8, (uint32_t)((j / STG64 - 1) & 1));
                mbar_expect(f0 + s * 8, SLOT64 - 512);
                bulkcp(sbase + s * SLOT64, At + (size_t)j * AT_H, 21760, f0 + s * 8);
                bulkcp(sbase + s * SLOT64 + 21760, Bt + (size_t)(2 * j) * T64_H, 18432, f0 + s * 8);
            }
        }
    } else {
        const int wm = warp % 5, wn = warp / 5;
        wmma::fragment<wmma::accumulator, 16, 16, 16, float> acc[3];
#pragma unroll
        for (int j = 0; j < 3; j++) wmma::fill_fragment(acc[j], 0.f);
        for (int i = 0; i < KB2; i++) {
            int s = i % STG64;
            mbar_wait(f0 + s * 8, (uint32_t)((i / STG64) & 1));
            const __half* As = (const __half*)(raw + s * SLOT64);
            const __half* Bs = As + 10880;
#pragma unroll
            for (int kk = 0; kk < 128; kk += 16) {
                wmma::fragment<wmma::matrix_a, 16, 16, 16, __half, wmma::row_major> af;
                wmma::load_matrix_sync(af, As + (wm * 16) * 136 + kk, 136);
#pragma unroll
                for (int j = 0; j < 3; j++) {
                    wmma::fragment<wmma::matrix_b, 16, 16, 16, __half, wmma::row_major> bf;
                    wmma::load_matrix_sync(bf, Bs + kk * 72 + wn * 48 + j * 16, 72);
                    wmma::mma_sync(acc[j], af, bf, acc[j]);
                }
            }
            if (lane == 0) mbar_arrive(d0 + s * 8);
        }
        __syncthreads();
        float* Cw = (float*)raw + warp * 768;   // 16x48 per warp
#pragma unroll
        for (int j = 0; j < 3; j++)
            wmma::store_matrix_sync(Cw + j * 16, acc[j], 48, wmma::mem_row_major);
        __syncwarp();
        const float sc = 1.f / 256.f;
#pragma unroll
        for (int r = 0; r < 16; r++) {
            int node = row0 + wm * 16 + r;
#pragma unroll
            for (int q = 0; q < 2; q++) {
                int cc = lane + q * 32;
                if (cc >= 48) continue;
                int col = wn * 48 + cc;
                if (col >= 65) continue;
                float v = Cw[r * 48 + cc] * sc;
                if (ucol >= 0)
                    v = 2.f * v - __half2float(lin[(size_t)node * 384 + ucol + col]);
                __half hv = __float2half(v);
                lin[(size_t)node * 384 + ccol + col] = hv;
                if (Tout) Tout[t64i(node, col)] = hv;
            }
        }
        return;
    }
    __syncthreads();
}

// ---------------- bigGemm16: warp-specialized, BK=128 (enc prologue only) ----------------
__global__ void __launch_bounds__(192) bigGemm16(const __half* __restrict__ Bt,
                                                 __half* __restrict__ Tout,
                                                 float* __restrict__ out16,
                                                 const float* __restrict__ uptr,
                                                 int ustride, int uncols) {
    extern __shared__ __align__(16) char raw[];
    __shared__ __align__(8) uint64_t mbf[STG16], mbd[STG16];
    const int tid = threadIdx.x, warp = tid >> 5, lane = tid & 31;
    const int row0 = blockIdx.x * 80;
    uint32_t sbase = (uint32_t)__cvta_generic_to_shared(raw);
    uint32_t f0 = (uint32_t)__cvta_generic_to_shared(&mbf[0]);
    uint32_t d0 = (uint32_t)__cvta_generic_to_shared(&mbd[0]);
    const __half* At = g_A16 + (size_t)blockIdx.x * KB2 * AT_H;

    if (tid == 0)
        for (int s = 0; s < STG16; s++) { mbar_init(f0 + s * 8, 1); mbar_init(d0 + s * 8, 5); }
    __syncthreads();

    if (warp == 5) {
        if (lane == 0) {
            for (int j = 0; j < KB2; j++) {
                int s = j % STG16;
                if (j >= STG16) mbar_wait(d0 + s * 8, (uint32_t)((j / STG16 - 1) & 1));
                mbar_expect(f0 + s * 8, SLOT16);
                bulkcp(sbase + s * SLOT16, At + (size_t)j * AT_H, 21760, f0 + s * 8);
                bulkcp(sbase + s * SLOT16 + 21760, Bt + (size_t)(2 * j) * T16_H, 6144, f0 + s * 8);
            }
        }
    } else {
        wmma::fragment<wmma::accumulator, 16, 16, 16, float> acc;
        wmma::fill_fragment(acc, 0.f);
        for (int i = 0; i < KB2; i++) {
            int s = i % STG16;
            mbar_wait(f0 + s * 8, (uint32_t)((i / STG16) & 1));
            const __half* As = (const __half*)(raw + s * SLOT16);
            const __half* Bs = As + 10880;
#pragma unroll
            for (int kk = 0; kk < 128; kk += 16) {
                wmma::fragment<wmma::matrix_a, 16, 16, 16, __half, wmma::row_major> af;
                wmma::load_matrix_sync(af, As + (warp * 16) * 136 + kk, 136);
                wmma::fragment<wmma::matrix_b, 16, 16, 16, __half, wmma::row_major> bf;
                wmma::load_matrix_sync(bf, Bs + kk * 24, 24);
                wmma::mma_sync(acc, af, bf, acc);
            }
            if (lane == 0) mbar_arrive(d0 + s * 8);
        }
        __syncthreads();
        float* Cw = (float*)raw + warp * 256;
        wmma::store_matrix_sync(Cw, acc, 16, wmma::mem_row_major);
        __syncwarp();
        if (lane < 16) {
            const float sc = 1.f / 256.f;
#pragma unroll
            for (int r = 0; r < 16; r++) {
                int node = row0 + warp * 16 + r;
                int col = lane;
                float v = Cw[r * 16 + col] * sc;
                if (uptr && col < uncols)
                    v = 2.f * v - uptr[(size_t)node * ustride + col];
                else if (uptr)
                    v = 2.f * v;
                out16[(size_t)node * 16 + col] = v;
                if (Tout) Tout[t16i(node, col)] = __float2half(v);
            }
        }
        return;
    }
    __syncthreads();
}

// ---------------- gates GEMM (wmma) ----------------
__global__ void __launch_bounds__(320) wgemmGatesT(const __half* __restrict__ lin1,
                                                   __half* __restrict__ lin2,
                                                   const __half* __restrict__ Wh,
                                                   const float* __restrict__ bias, int dec) {
    extern __shared__ __align__(16) char raw[];
    __half* As = (__half*)raw;                       // 80 x 392
    __half* Bs = (__half*)(raw + 80 * 392 * 2);      // 384 x 136
    const int tid = threadIdx.x, warp = tid >> 5, lane = tid & 31;
    const int row0 = blockIdx.x * 80;

    for (int i = tid; i < 80 * 48; i += 320) {
        int r = i / 48, q = i % 48;
        ((float4*)(As + r * 392))[q] = ((const float4*)(lin1 + (size_t)(row0 + r) * 384))[q];
    }
    for (int i = tid; i < 384 * 16; i += 320) {
        int r = i / 16, q = i % 16;
        ((float4*)(Bs + r * 136))[q] = ((const float4*)(Wh + (size_t)r * 128))[q];
    }
    __syncthreads();

    const int wm = warp % 5, wn = warp / 5;
    wmma::fragment<wmma::accumulator, 16, 16, 16, float> acc[4];
#pragma unroll
    for (int j = 0; j < 4; j++) wmma::fill_fragment(acc[j], 0.f);
#pragma unroll 4
    for (int k = 0; k < 384; k += 16) {
        wmma::fragment<wmma::matrix_a, 16, 16, 16, __half, wmma::row_major> af;
        wmma::load_matrix_sync(af, As + (wm * 16) * 392 + k, 392);
#pragma unroll
        for (int j = 0; j < 4; j++) {
            wmma::fragment<wmma::matrix_b, 16, 16, 16, __half, wmma::row_major> bf;
            wmma::load_matrix_sync(bf, Bs + k * 136 + wn * 64 + j * 16, 136);
            wmma::mma_sync(acc[j], af, bf, acc[j]);
        }
    }
    __syncthreads();
    float* Cw = (float*)Bs + warp * 1024;
#pragma unroll
    for (int j = 0; j < 4; j++)
        wmma::store_matrix_sync(Cw + j * 16, acc[j], 64, wmma::mem_row_major);
    __syncwarp();

#pragma unroll
    for (int r = 0; r < 16; r++) {
        int node = row0 + wm * 16 + r;
        const __half* Ar = As + (wm * 16 + r) * 392;
        __half* L2 = lin2 + (size_t)node * 384;
#pragma unroll
        for (int hh = 0; hh < 2; hh++) {
            int c = lane + hh * 32;
            float v = Cw[r * 64 + c] + bias[wn * 64 + c];
            float sig = 1.f / (1.f + __expf(-v));
            if (wn == 0) {
                __half rh = __float2half(sig * g_h[node * 64 + c]);
                g_Prh[t64i(node, c)] = rh;
                if (!dec) {
                    L2[c] = Ar[c];  L2[64 + c] = rh;
                    L2[128 + c] = Ar[128 + c];  L2[256 + c] = Ar[256 + c];
                } else {
                    L2[1 + c] = rh;
                    if (c == 0) { L2[0] = Ar[0]; L2[128] = Ar[128]; L2[256] = Ar[256]; }
                }
            } else {
                g_u[node * 64 + c] = sig;
            }
        }
    }
}

// ---------------- cand GEMM (wmma) + GRU update ----------------
__global__ void __launch_bounds__(320) wgemmCandT(const __half* __restrict__ lin2,
                                                  const __half* __restrict__ Wch,
                                                  const float* __restrict__ bias) {
    extern __shared__ __align__(16) char raw[];
    __half* As = (__half*)raw;                       // 80 x 392
    __half* Bs = (__half*)(raw + 80 * 392 * 2);      // 384 x 72
    const int tid = threadIdx.x, warp = tid >> 5, lane = tid & 31;
    const int row0 = blockIdx.x * 80;

    for (int i = tid; i < 80 * 48; i += 320) {
        int r = i / 48, q = i % 48;
        ((float4*)(As + r * 392))[q] = ((const float4*)(lin2 + (size_t)(row0 + r) * 384))[q];
    }
    for (int i = tid; i < 384 * 8; i += 320) {
        int r = i / 8, q = i % 8;
        ((float4*)(Bs + r * 72))[q] = ((const float4*)(Wch + (size_t)r * 64))[q];
    }
    __syncthreads();

    const int wm = warp % 5, wn = warp / 5;
    wmma::fragment<wmma::accumulator, 16, 16, 16, float> acc[2];
    wmma::fill_fragment(acc[0], 0.f);
    wmma::fill_fragment(acc[1], 0.f);
#pragma unroll 4
    for (int k = 0; k < 384; k += 16) {
        wmma::fragment<wmma::matrix_a, 16, 16, 16, __half, wmma::row_major> af;
        wmma::load_matrix_sync(af, As + (wm * 16) * 392 + k, 392);
#pragma unroll
        for (int j = 0; j < 2; j++) {
            wmma::fragment<wmma::matrix_b, 16, 16, 16, __half, wmma::row_major> bf;
            wmma::load_matrix_sync(bf, Bs + k * 72 + wn * 32 + j * 16, 72);
            wmma::mma_sync(acc[j], af, bf, acc[j]);
        }
    }
    __syncthreads();
    float* Cw = (float*)Bs + warp * 512;
    wmma::store_matrix_sync(Cw, acc[0], 32, wmma::mem_row_major);
    wmma::store_matrix_sync(Cw + 16, acc[1], 32, wmma::mem_row_major);
    __syncwarp();

#pragma unroll
    for (int r = 0; r < 16; r++) {
        int node = row0 + wm * 16 + r;
        int col = wn * 32 + lane;
        float v = Cw[r * 32 + lane] + bias[col];
        float c = tanhf(v);
        float u = g_u[node * 64 + col];
        float hOld = g_h[node * 64 + col];
        g_h[node * 64 + col] = u * hOld + (1.f - u) * c;
    }
}

// ---------------- prediction ----------------
__global__ void predKernel(const float* __restrict__ Wp, const float* __restrict__ bp,
                           float* __restrict__ out, int t) {
    int gwarp = (blockIdx.x * blockDim.x + threadIdx.x) >> 5;
    int lane = threadIdx.x & 31;
    if (gwarp >= NW) return;
    float s = g_h[gwarp * 64 + lane] * Wp[lane] + g_h[gwarp * 64 + 32 + lane] * Wp[32 + lane];
#pragma unroll
    for (int o = 16; o; o >>= 1) s += __shfl_xor_sync(0xFFFFFFFFu, s, o);
    if (lane == 0) {
        float val = s + bp[0];
        out[gwarp * 12 + t] = val;
        g_x[gwarp] = val;
    }
}

// ---------------- launch ----------------
extern "C" void kernel_launch(void* const* d_in, const int* in_sizes, int n_in,
                              void* d_out, int out_size) {
    const float* inputs = (const float*)d_in[0];
    const float* adj    = (const float*)d_in[2];
    const float* W_emb  = (const float*)d_in[3];
    const float* b_emb  = (const float*)d_in[4];
    const float* Wg_e   = (const float*)d_in[5];
    const float* bg_e   = (const float*)d_in[6];
    const float* Wc_e   = (const float*)d_in[7];
    const float* bc_e   = (const float*)d_in[8];
    const float* Wg_d   = (const float*)d_in[9];
    const float* bg_d   = (const float*)d_in[10];
    const float* Wc_d   = (const float*)d_in[11];
    const float* bc_d   = (const float*)d_in[12];
    const float* W_pred = (const float*)d_in[13];
    const float* b_pred = (const float*)d_in[14];
    float* out = (float*)d_out;

    __half *Ph, *Prh, *Pt, *Px0, *Px1, *lin1, *lin2;
    __half *Wge, *Wce, *Wgd, *Wcd;
    float *X1E, *X2E;
    cudaGetSymbolAddress((void**)&Ph, g_Ph);
    cudaGetSymbolAddress((void**)&Prh, g_Prh);
    cudaGetSymbolAddress((void**)&Pt, g_Pt);
    cudaGetSymbolAddress((void**)&Px0, g_Px0);
    cudaGetSymbolAddress((void**)&Px1, g_Px1);
    cudaGetSymbolAddress((void**)&lin1, g_lin1);
    cudaGetSymbolAddress((void**)&lin2, g_lin2);
    cudaGetSymbolAddress((void**)&Wge, g_Wge);
    cudaGetSymbolAddress((void**)&Wce, g_Wce);
    cudaGetSymbolAddress((void**)&Wgd, g_Wgd);
    cudaGetSymbolAddress((void**)&Wcd, g_Wcd);
    cudaGetSymbolAddress((void**)&X1E, g_X1E);
    cudaGetSymbolAddress((void**)&X2E, g_X2E);

    const int sm64 = STG64 * SLOT64;                 // 203520
    const int sm16 = STG16 * SLOT16;                 // 223232
    const int smG  = 80 * 392 * 2 + 384 * 136 * 2;   // 167168
    const int smC  = 80 * 392 * 2 + 384 * 72 * 2;    // 118016
    cudaFuncSetAttribute(bigGemm64, cudaFuncAttributeMaxDynamicSharedMemorySize, sm64);
    cudaFuncSetAttribute(bigGemm65, cudaFuncAttributeMaxDynamicSharedMemorySize, sm64);
    cudaFuncSetAttribute(bigGemm16, cudaFuncAttributeMaxDynamicSharedMemorySize, sm16);
    cudaFuncSetAttribute(wgemmGatesT, cudaFuncAttributeMaxDynamicSharedMemorySize, smG);
    cudaFuncSetAttribute(wgemmCandT, cudaFuncAttributeMaxDynamicSharedMemorySize, smC);

    convA<<<4096, 256>>>(adj);
    initState<<<(NW * 64 + 255) / 256, 256>>>();
    buildX<<<(NW * 16 + 255) / 256, 256>>>(inputs);
    convW<<<(384 * 128 + 255) / 256, 256>>>(Wg_e, Wge, 128, 128);
    convW<<<(384 * 64 + 255) / 256, 256>>>(Wc_e, Wce, 128, 64);
    convW<<<(384 * 128 + 255) / 256, 256>>>(Wg_d, Wgd, 65, 128);
    convW<<<(384 * 64 + 255) / 256, 256>>>(Wc_d, Wcd, 65, 64);
    bigGemm16<<<MBK, 192, sm16>>>(Px0, Px1, X1E, nullptr, 0, 0);
    bigGemm16<<<MBK, 192, sm16>>>(Px1, nullptr, X2E, inputs, 12, 12);

    for (int t = 0; t < 12; t++) {
        buildEncGate<<<(NW * 64 + 255) / 256, 256>>>(inputs, W_emb, b_emb, t);
        bigGemm64<<<MBK, 352, sm64>>>(Ph, Pt, lin1, 192, -1);
        bigGemm64<<<MBK, 352, sm64>>>(Pt, nullptr, lin1, 320, 64);
        wgemmGatesT<<<MBK, 320, smG>>>(lin1, lin2, Wge, bg_e, 0);
        bigGemm64<<<MBK, 352, sm64>>>(Prh, Pt, lin2, 192, -1);
        bigGemm64<<<MBK, 352, sm64>>>(Pt, nullptr, lin2, 320, 64);
        wgemmCandT<<<MBK, 320, smC>>>(lin2, Wce, bc_e);
    }
    for (int t = 0; t < 12; t++) {
        buildDecGate<<<(NW * 72 + 255) / 256, 256>>>();
        bigGemm65<<<MBK, 352, sm64>>>(Ph, Pt, lin1, 128, -1);   // A@[x|h] -> 65 cols
        bigGemm65<<<MBK, 352, sm64>>>(Pt, nullptr, lin1, 256, 0);
        wgemmGatesT<<<MBK, 320, smG>>>(lin1, lin2, Wgd, bg_d, 1);
        bigGemm64<<<MBK, 352, sm64>>>(Prh, Pt, lin2, 129, -1);
        bigGemm64<<<MBK, 352, sm64>>>(Pt, nullptr, lin2, 257, 1);
        wgemmCandT<<<MBK, 320, smC>>>(lin2, Wcd, bc_d);
        predKernel<<<(NW + 3) / 4, 128>>>(W_pred, b_pred, out, t);
    }
}